// round 16
// baseline (speedup 1.0000x reference)
#include <cuda_runtime.h>
#include <cstdint>

#define S_  16
#define A_  16
#define DA_ 128
#define DS_ 128
#define H_  64
#define TB  64
#define NTHREADS 128
#define B_MAX 2048
#define NCTA_PERSIST 296

#define H_LD 68

// packed expert image (word offsets)
#define PK_W1 0
#define PK_W2 8192
#define PK_W3 12288
#define PK_B1 20480
#define PK_B2 20544
#define PK_B3 20608
#define PK_STRIDE 20736

// SMEM byte offsets
#define SM_W1 0
#define SM_W2 32768
#define SM_W3 49152
#define SM_H  81920
#define SM_B1 99328
#define SM_B2 99584
#define SM_B3 99840
#define SM_TK 100096
#define SMEM_BYTES 100352

__device__ int g_cnt[S_];
__device__ int g_list[S_][A_];
__device__ int g_sperm[S_];
__device__ int g_ticket;
__device__ float    g_wpack[256 * PK_STRIDE];
__device__ unsigned g_apack[(size_t)B_MAX * A_ * DA_];   // fragment-packed A tiles

__device__ __forceinline__ unsigned f2tf(float f) {
    unsigned u;
    asm("cvt.rna.tf32.f32 %0, %1;" : "=r"(u) : "f"(f));
    return u;
}

// Shared mask decode (deterministic; used by mask block and by weight blocks
// for early-exit). Reads exactly 256 bytes — safe for all dtype interpretations.
__device__ __forceinline__ int mask_value(const unsigned* rel, const unsigned* sv, int e) {
    bool allint = true, allfloat = true;
    for (int i = 0; i < 64; i++) {
        unsigned u = sv[i];
        if (u > 1u) allint = false;
        if (!(u == 0u || u == 0x3F800000u)) allfloat = false;
    }
    if (allint)   return ((const int*)rel)[e] != 0;
    if (allfloat) return ((const float*)rel)[e] != 0.0f;
    return ((const unsigned char*)rel)[e] != 0;
}

// One merged prep kernel.
// Blocks [0,256): weight fragment packing (skip inactive experts).
// Blocks [256, 256+nab): A fragment packing per (mblock32, a) tile.
// Block 256+nab: mask compaction + s-permutation + ticket reset.
__global__ void prep_pack(const float* __restrict__ W1, const float* __restrict__ b1,
                          const float* __restrict__ W2, const float* __restrict__ b2,
                          const float* __restrict__ W3, const float* __restrict__ b3,
                          const float* __restrict__ act,
                          const unsigned* __restrict__ rel, int nab) {
    __shared__ float sbuf[8192];
    const int bx = blockIdx.x;
    const int tid = threadIdx.x;

    if (bx < 256) {
        // ---- local activity check (early-exit saves ~half the traffic) ----
        __shared__ unsigned sv[64];
        __shared__ int s_active;
        if (tid < 64) sv[tid] = rel[tid];
        __syncthreads();
        if (tid == 0) s_active = mask_value(rel, sv, bx);
        __syncthreads();
        if (!s_active) return;

        const int e = bx;
        float* dst = g_wpack + (size_t)e * PK_STRIDE;
        // ---- W1: K=128 x N=64, NP=4 ----
        {
            const float4* s = (const float4*)(W1 + (size_t)e * (DA_ * H_));
            for (int i = tid; i < 2048; i += 256) ((float4*)sbuf)[i] = s[i];
            __syncthreads();
            for (int cell = tid; cell < 2048; cell += 256) {
                int lane = cell & 31, g = cell >> 5;
                int kc = g >> 2, np = g & 3;
                int kb = kc * 8 + (lane & 3), nb = np * 16 + (lane >> 2);
                uint4 u;
                u.x = f2tf(sbuf[(kb + 0) * 64 + nb]);
                u.y = f2tf(sbuf[(kb + 4) * 64 + nb]);
                u.z = f2tf(sbuf[(kb + 0) * 64 + nb + 8]);
                u.w = f2tf(sbuf[(kb + 4) * 64 + nb + 8]);
                ((uint4*)(dst + PK_W1))[cell] = u;
            }
            __syncthreads();
        }
        // ---- W2: K=64 x N=64, NP=4 ----
        {
            const float4* s = (const float4*)(W2 + (size_t)e * (H_ * H_));
            for (int i = tid; i < 1024; i += 256) ((float4*)sbuf)[i] = s[i];
            __syncthreads();
            for (int cell = tid; cell < 1024; cell += 256) {
                int lane = cell & 31, g = cell >> 5;
                int kc = g >> 2, np = g & 3;
                int kb = kc * 8 + (lane & 3), nb = np * 16 + (lane >> 2);
                uint4 u;
                u.x = f2tf(sbuf[(kb + 0) * 64 + nb]);
                u.y = f2tf(sbuf[(kb + 4) * 64 + nb]);
                u.z = f2tf(sbuf[(kb + 0) * 64 + nb + 8]);
                u.w = f2tf(sbuf[(kb + 4) * 64 + nb + 8]);
                ((uint4*)(dst + PK_W2))[cell] = u;
            }
            __syncthreads();
        }
        // ---- W3: K=64 x N=128, NP=8 ----
        {
            const float4* s = (const float4*)(W3 + (size_t)e * (H_ * DS_));
            for (int i = tid; i < 2048; i += 256) ((float4*)sbuf)[i] = s[i];
            __syncthreads();
            for (int cell = tid; cell < 2048; cell += 256) {
                int lane = cell & 31, g = cell >> 5;
                int kc = g >> 3, np = g & 7;
                int kb = kc * 8 + (lane & 3), nb = np * 16 + (lane >> 2);
                uint4 u;
                u.x = f2tf(sbuf[(kb + 0) * 128 + nb]);
                u.y = f2tf(sbuf[(kb + 4) * 128 + nb]);
                u.z = f2tf(sbuf[(kb + 0) * 128 + nb + 8]);
                u.w = f2tf(sbuf[(kb + 4) * 128 + nb + 8]);
                ((uint4*)(dst + PK_W3))[cell] = u;
            }
        }
        if (tid < 64)        dst[PK_B1 + tid]        = b1[e * H_  + tid];
        else if (tid < 128)  dst[PK_B2 + tid - 64]   = b2[e * H_  + tid - 64];
        else if (tid < 256)  dst[PK_B3 + tid - 128]  = b3[e * DS_ + tid - 128];
    } else if (bx < 256 + nab) {
        const int t = bx - 256;
        const int mb = t >> 4, a = t & 15;
        const float* srcb = act + ((size_t)(mb * 32) * A_ + a) * DA_;
        for (int i = tid; i < 1024; i += 256) {
            int row = i >> 5, c4 = i & 31;
            *(float4*)(sbuf + row * 128 + c4 * 4) =
                *(const float4*)(srcb + (size_t)row * A_ * DA_ + c4 * 4);
        }
        __syncthreads();
        unsigned* dst = g_apack + ((size_t)mb * A_ + a) * 4096;
        for (int cell = tid; cell < 1024; cell += 256) {
            int lane = cell & 31, mt = (cell >> 5) & 1, kc = cell >> 6;
            int rl = mt * 16 + (lane >> 2), k = kc * 8 + (lane & 3);
            uint4 u;
            u.x = f2tf(sbuf[rl * 128 + k]);
            u.y = f2tf(sbuf[(rl + 8) * 128 + k]);
            u.z = f2tf(sbuf[rl * 128 + k + 4]);
            u.w = f2tf(sbuf[(rl + 8) * 128 + k + 4]);
            ((uint4*)dst)[cell] = u;
        }
    } else {
        // ---- mask compaction + sperm + ticket reset ----
        __shared__ unsigned sv[64];
        __shared__ int sm_[S_ * A_];
        if (tid < 64) sv[tid] = rel[tid];
        __syncthreads();
        if (tid < S_ * A_) sm_[tid] = 0;
        __syncthreads();
        if (tid == 0) {
            g_ticket = 0;
            for (int e = 0; e < S_ * A_; e++) sm_[e] = mask_value(rel, sv, e);
            int cnt[S_];
            for (int s = 0; s < S_; s++) {
                int c = 0;
                for (int a = 0; a < A_; a++)
                    if (sm_[s * A_ + a]) g_list[s][c++] = a;
                g_cnt[s] = c;
                cnt[s] = c;
            }
            int perm[S_];
            for (int i = 0; i < S_; i++) perm[i] = i;
            for (int i = 0; i < S_ - 1; i++) {
                int best = i;
                for (int j = i + 1; j < S_; j++)
                    if (cnt[perm[j]] > cnt[perm[best]]) best = j;
                int tt = perm[i]; perm[i] = perm[best]; perm[best] = tt;
            }
            for (int i = 0; i < S_; i++) g_sperm[i] = perm[i];
        }
    }
}

__device__ __forceinline__ void cpa16(uint32_t dst, const void* src) {
    asm volatile("cp.async.cg.shared.global [%0], [%1], 16;" :: "r"(dst), "l"(src));
}
#define CP_COMMIT() asm volatile("cp.async.commit_group;" ::: "memory")
#define CP_WAIT2()  asm volatile("cp.async.wait_group 2;" ::: "memory")

__device__ __forceinline__ void mma_tf32(float& d0, float& d1, float& d2, float& d3,
                                         unsigned a0, unsigned a1, unsigned a2, unsigned a3,
                                         unsigned b0, unsigned b1) {
    asm volatile(
        "mma.sync.aligned.m16n8k8.row.col.f32.tf32.tf32.f32 "
        "{%0,%1,%2,%3}, {%4,%5,%6,%7}, {%8,%9}, {%0,%1,%2,%3};"
        : "+f"(d0), "+f"(d1), "+f"(d2), "+f"(d3)
        : "r"(a0), "r"(a1), "r"(a2), "r"(a3), "r"(b0), "r"(b1));
}

// --- staging: pure linear copies from packed image (128 threads) ---
__device__ __forceinline__ void stage1(uint32_t sb, int tid, const float* src) {
    #pragma unroll
    for (int it = 0; it < 16; it++) {
        int i = tid + it * NTHREADS;
        cpa16(sb + SM_W1 + i * 16, src + PK_W1 + i * 4);
    }
    if (tid < 16) cpa16(sb + SM_B1 + tid * 16, src + PK_B1 + tid * 4);
}
__device__ __forceinline__ void stage2(uint32_t sb, int tid, const float* src) {
    #pragma unroll
    for (int it = 0; it < 8; it++) {
        int i = tid + it * NTHREADS;
        cpa16(sb + SM_W2 + i * 16, src + PK_W2 + i * 4);
    }
    if (tid < 16) cpa16(sb + SM_B2 + tid * 16, src + PK_B2 + tid * 4);
}
__device__ __forceinline__ void stage3(uint32_t sb, int tid, const float* src) {
    #pragma unroll
    for (int it = 0; it < 16; it++) {
        int i = tid + it * NTHREADS;
        cpa16(sb + SM_W3 + i * 16, src + PK_W3 + i * 4);
    }
    if (tid < 32) cpa16(sb + SM_B3 + tid * 16, src + PK_B3 + tid * 4);
}

__global__ __launch_bounds__(NTHREADS, 2)
void expert_kernel(const float* __restrict__ state, float* __restrict__ out,
                   int nitems)
{
    extern __shared__ char smem[];
    const uint32_t sb = (uint32_t)__cvta_generic_to_shared(smem);
    const unsigned* W1u = (const unsigned*)(smem + SM_W1);
    const unsigned* W2u = (const unsigned*)(smem + SM_W2);
    const unsigned* W3u = (const unsigned*)(smem + SM_W3);
    float*    hs  = (float*)(smem + SM_H);
    const unsigned* hu = (const unsigned*)(smem + SM_H);
    const float* b1s = (const float*)(smem + SM_B1);
    const float* b2s = (const float*)(smem + SM_B2);
    const float* b3s = (const float*)(smem + SM_B3);
    int* tks = (int*)(smem + SM_TK);

    const int tid  = threadIdx.x;
    const int lane = tid & 31;
    const int warp = tid >> 5;
    const int wm   = warp & 1;      // 2 warp-rows (m32)
    const int wn   = warp >> 1;     // 2 warp-cols
    const int r    = lane >> 2;
    const int q    = lane & 3;
    const int mrow0 = wm * 32 + r;

    for (;;) {
        // ---- dynamic work ticket ----
        if (tid == 0) tks[0] = atomicAdd(&g_ticket, 1);
        __syncthreads();
        const int item = tks[0];
        if (item >= nitems) break;
        const int s  = g_sperm[item >> 5];
        const int b0 = (item & 31) * TB;
        const int bxq = item & 31;
        __syncthreads();   // tks consumed; also: prior item fully done with smem

        float acc[2][8][4];
        #pragma unroll
        for (int mt = 0; mt < 2; mt++)
            #pragma unroll
            for (int nt = 0; nt < 8; nt++)
                #pragma unroll
                for (int c = 0; c < 4; c++) acc[mt][nt][c] = 0.0f;

        const int cnt = g_cnt[s];

        if (cnt > 0) {
            const float* src = g_wpack + (size_t)(s * A_ + g_list[s][0]) * PK_STRIDE;
            stage1(sb, tid, src); CP_COMMIT();
            stage2(sb, tid, src); CP_COMMIT();
            stage3(sb, tid, src); CP_COMMIT();
        }

        for (int j = 0; j < cnt; j++) {
            const int a = g_list[s][j];
            const float* srcn = (j + 1 < cnt)
                ? g_wpack + (size_t)(s * A_ + g_list[s][j + 1]) * PK_STRIDE : nullptr;

            CP_WAIT2();          // W1(j), b1(j) landed
            __syncthreads();     // publish W1; everyone done with h/W3 from prev iter

            // ---- GEMM1: h1 = relu(A @ W1 + b1), M64 N64 K128 ----
            {
                float d[2][4][4];
                #pragma unroll
                for (int mt = 0; mt < 2; mt++)
                    #pragma unroll
                    for (int nt = 0; nt < 4; nt++)
                        { d[mt][nt][0]=0; d[mt][nt][1]=0; d[mt][nt][2]=0; d[mt][nt][3]=0; }

                const unsigned* atile =
                    g_apack + ((size_t)(bxq * 2 + wm) * A_ + a) * 4096;

                #pragma unroll 4
                for (int kc = 0; kc < 16; kc++) {
                    uint4 A0 = *(const uint4*)(atile + ((kc * 2 + 0) * 32 + lane) * 4);
                    uint4 A1 = *(const uint4*)(atile + ((kc * 2 + 1) * 32 + lane) * 4);
                    uint4 p0 = *(const uint4*)(W1u + ((kc * 4 + wn * 2 + 0) * 32 + lane) * 4);
                    uint4 p1 = *(const uint4*)(W1u + ((kc * 4 + wn * 2 + 1) * 32 + lane) * 4);
                    unsigned bf[4][2];
                    bf[0][0] = p0.x; bf[0][1] = p0.y; bf[1][0] = p0.z; bf[1][1] = p0.w;
                    bf[2][0] = p1.x; bf[2][1] = p1.y; bf[3][0] = p1.z; bf[3][1] = p1.w;
                    #pragma unroll
                    for (int nt = 0; nt < 4; nt++) {
                        mma_tf32(d[0][nt][0], d[0][nt][1], d[0][nt][2], d[0][nt][3],
                                 A0.x, A0.y, A0.z, A0.w, bf[nt][0], bf[nt][1]);
                        mma_tf32(d[1][nt][0], d[1][nt][1], d[1][nt][2], d[1][nt][3],
                                 A1.x, A1.y, A1.z, A1.w, bf[nt][0], bf[nt][1]);
                    }
                }
                #pragma unroll
                for (int mt = 0; mt < 2; mt++)
                    #pragma unroll
                    for (int nt = 0; nt < 4; nt++) {
                        int col = wn * 32 + nt * 8 + 2 * q;
                        float bb0 = b1s[col], bb1 = b1s[col + 1];
                        int row = mrow0 + mt * 16;
                        uint2 v0 = { f2tf(fmaxf(d[mt][nt][0] + bb0, 0.0f)),
                                     f2tf(fmaxf(d[mt][nt][1] + bb1, 0.0f)) };
                        uint2 v1 = { f2tf(fmaxf(d[mt][nt][2] + bb0, 0.0f)),
                                     f2tf(fmaxf(d[mt][nt][3] + bb1, 0.0f)) };
                        *(uint2*)(hs + row * H_LD + col)       = v0;
                        *(uint2*)(hs + (row + 8) * H_LD + col) = v1;
                    }
            }
            __syncthreads();     // ALL warps done reading W1(j)/b1(j) before overwrite
            if (srcn) { stage1(sb, tid, srcn); }
            CP_COMMIT();
            CP_WAIT2();          // W2(j), b2(j) landed
            __syncthreads();     // publish W2; h1 visible to all warps

            // ---- GEMM2: h2 = relu(h1 @ W2 + b2), M64 N64 K64 (in-place h) ----
            {
                unsigned a2r[8][2][4];
                #pragma unroll
                for (int kc = 0; kc < 8; kc++) {
                    const int k0 = kc * 8;
                    #pragma unroll
                    for (int mt = 0; mt < 2; mt++) {
                        const unsigned* hb = hu + (mrow0 + mt * 16) * H_LD + k0 + q;
                        a2r[kc][mt][0] = hb[0];
                        a2r[kc][mt][1] = hb[8 * H_LD];
                        a2r[kc][mt][2] = hb[4];
                        a2r[kc][mt][3] = hb[8 * H_LD + 4];
                    }
                }
                __syncthreads();   // all reads of h1 done; safe to overwrite

                float d[2][4][4];
                #pragma unroll
                for (int mt = 0; mt < 2; mt++)
                    #pragma unroll
                    for (int nt = 0; nt < 4; nt++)
                        { d[mt][nt][0]=0; d[mt][nt][1]=0; d[mt][nt][2]=0; d[mt][nt][3]=0; }
                #pragma unroll
                for (int kc = 0; kc < 8; kc++) {
                    unsigned bf[4][2];
                    uint4 p0 = *(const uint4*)(W2u + ((kc * 4 + wn * 2 + 0) * 32 + lane) * 4);
                    uint4 p1 = *(const uint4*)(W2u + ((kc * 4 + wn * 2 + 1) * 32 + lane) * 4);
                    bf[0][0] = p0.x; bf[0][1] = p0.y; bf[1][0] = p0.z; bf[1][1] = p0.w;
                    bf[2][0] = p1.x; bf[2][1] = p1.y; bf[3][0] = p1.z; bf[3][1] = p1.w;
                    #pragma unroll
                    for (int mt = 0; mt < 2; mt++)
                        #pragma unroll
                        for (int nt = 0; nt < 4; nt++)
                            mma_tf32(d[mt][nt][0], d[mt][nt][1], d[mt][nt][2], d[mt][nt][3],
                                     a2r[kc][mt][0], a2r[kc][mt][1], a2r[kc][mt][2], a2r[kc][mt][3],
                                     bf[nt][0], bf[nt][1]);
                }
                #pragma unroll
                for (int mt = 0; mt < 2; mt++)
                    #pragma unroll
                    for (int nt = 0; nt < 4; nt++) {
                        int col = wn * 32 + nt * 8 + 2 * q;
                        float bb0 = b2s[col], bb1 = b2s[col + 1];
                        int row = mrow0 + mt * 16;
                        uint2 v0 = { f2tf(fmaxf(d[mt][nt][0] + bb0, 0.0f)),
                                     f2tf(fmaxf(d[mt][nt][1] + bb1, 0.0f)) };
                        uint2 v1 = { f2tf(fmaxf(d[mt][nt][2] + bb0, 0.0f)),
                                     f2tf(fmaxf(d[mt][nt][3] + bb1, 0.0f)) };
                        *(uint2*)(hs + row * H_LD + col)       = v0;
                        *(uint2*)(hs + (row + 8) * H_LD + col) = v1;
                    }
            }
            __syncthreads();     // ALL warps done reading W2(j)/b2(j) before overwrite
            if (srcn) { stage2(sb, tid, srcn); }
            CP_COMMIT();
            CP_WAIT2();          // W3(j), b3(j) landed
            __syncthreads();     // publish W3; h2 visible to all warps

            // ---- GEMM3: acc += relu(h2 @ W3 + b3), M64 N128 K64 ----
            {
                float d[2][8][4];
                #pragma unroll
                for (int mt = 0; mt < 2; mt++)
                    #pragma unroll
                    for (int nt = 0; nt < 8; nt++)
                        { d[mt][nt][0]=0; d[mt][nt][1]=0; d[mt][nt][2]=0; d[mt][nt][3]=0; }
                #pragma unroll 2
                for (int kc = 0; kc < 8; kc++) {
                    const int k0 = kc * 8;
                    unsigned af[2][4], bf[8][2];
                    #pragma unroll
                    for (int mt = 0; mt < 2; mt++) {
                        const unsigned* hb = hu + (mrow0 + mt * 16) * H_LD + k0 + q;
                        af[mt][0] = hb[0];
                        af[mt][1] = hb[8 * H_LD];
                        af[mt][2] = hb[4];
                        af[mt][3] = hb[8 * H_LD + 4];
                    }
                    #pragma unroll
                    for (int pp = 0; pp < 4; pp++) {
                        uint4 p = *(const uint4*)(W3u + ((kc * 8 + wn * 4 + pp) * 32 + lane) * 4);
                        bf[2 * pp][0]     = p.x; bf[2 * pp][1]     = p.y;
                        bf[2 * pp + 1][0] = p.z; bf[2 * pp + 1][1] = p.w;
                    }
                    #pragma unroll
                    for (int mt = 0; mt < 2; mt++)
                        #pragma unroll
                        for (int nt = 0; nt < 8; nt++)
                            mma_tf32(d[mt][nt][0], d[mt][nt][1], d[mt][nt][2], d[mt][nt][3],
                                     af[mt][0], af[mt][1], af[mt][2], af[mt][3],
                                     bf[nt][0], bf[nt][1]);
                }
                #pragma unroll
                for (int mt = 0; mt < 2; mt++)
                    #pragma unroll
                    for (int nt = 0; nt < 8; nt++) {
                        int col = wn * 64 + nt * 8 + 2 * q;
                        float bb0 = b3s[col], bb1 = b3s[col + 1];
                        acc[mt][nt][0] += fmaxf(d[mt][nt][0] + bb0, 0.0f);
                        acc[mt][nt][1] += fmaxf(d[mt][nt][1] + bb1, 0.0f);
                        acc[mt][nt][2] += fmaxf(d[mt][nt][2] + bb0, 0.0f);
                        acc[mt][nt][3] += fmaxf(d[mt][nt][3] + bb1, 0.0f);
                    }
            }
            __syncthreads();     // ALL warps done reading W3(j)/b3(j)/h2 before overwrite
            if (srcn) { stage3(sb, tid, srcn); }
            CP_COMMIT();
        }

        // ---- epilogue: out = state + diff ----
        #pragma unroll
        for (int mt = 0; mt < 2; mt++)
            #pragma unroll
            for (int nt = 0; nt < 8; nt++) {
                int row = b0 + mrow0 + mt * 16;
                int col = wn * 64 + nt * 8 + 2 * q;
                size_t base = ((size_t)row * S_ + s) * DS_ + col;
                float2 s0 = *(const float2*)(state + base);
                float2 s1 = *(const float2*)(state + base + 8 * (size_t)S_ * DS_);
                float2 o0 = { s0.x + acc[mt][nt][0], s0.y + acc[mt][nt][1] };
                float2 o1 = { s1.x + acc[mt][nt][2], s1.y + acc[mt][nt][3] };
                *(float2*)(out + base)                        = o0;
                *(float2*)(out + base + 8 * (size_t)S_ * DS_) = o1;
            }
        __syncthreads();   // all warps done with W3/h before next item's staging
    }
}

extern "C" void kernel_launch(void* const* d_in, const int* in_sizes, int n_in,
                              void* d_out, int out_size)
{
    const float* state = (const float*)d_in[0];
    const float* act   = (const float*)d_in[1];
    const void*  rel   = d_in[2];
    const float* W1 = (const float*)d_in[3];
    const float* b1 = (const float*)d_in[4];
    const float* W2 = (const float*)d_in[5];
    const float* b2 = (const float*)d_in[6];
    const float* W3 = (const float*)d_in[7];
    const float* b3 = (const float*)d_in[8];
    float* out = (float*)d_out;

    const int B = in_sizes[0] / (S_ * DS_);
    const int nab = (B / 32) * A_;
    const int nitems = (B / TB) * S_;

    cudaFuncSetAttribute(expert_kernel,
                         cudaFuncAttributeMaxDynamicSharedMemorySize, SMEM_BYTES);

    prep_pack<<<256 + nab + 1, 256>>>(W1, b1, W2, b2, W3, b3, act,
                                      (const unsigned*)rel, nab);

    expert_kernel<<<NCTA_PERSIST, NTHREADS, SMEM_BYTES>>>(state, out, nitems);
}

// round 17
// speedup vs baseline: 2.0702x; 2.0702x over previous
#include <cuda_runtime.h>
#include <cstdint>

#define S_  16
#define A_  16
#define DA_ 128
#define DS_ 128
#define H_  64
#define TB  64
#define NTHREADS 128
#define B_MAX 2048
#define NCTA_PERSIST 296

#define H_LD 68

// packed expert image (word offsets)
#define PK_W1 0
#define PK_W2 8192
#define PK_W3 12288
#define PK_B1 20480
#define PK_B2 20544
#define PK_B3 20608
#define PK_STRIDE 20736

// SMEM byte offsets
#define SM_W1 0
#define SM_W2 32768
#define SM_W3 49152
#define SM_H  81920
#define SM_B1 99328
#define SM_B2 99584
#define SM_B3 99840
#define SM_TK 100096
#define SMEM_BYTES 100352

__device__ int g_cnt[S_];
__device__ int g_list[S_][A_];
__device__ int g_sperm[S_];
__device__ int g_ticket;
__device__ float    g_wpack[256 * PK_STRIDE];
__device__ unsigned g_apack[(size_t)B_MAX * A_ * DA_];   // fragment-packed A tiles

__device__ __forceinline__ unsigned f2tf(float f) {
    unsigned u;
    asm("cvt.rna.tf32.f32 %0, %1;" : "=r"(u) : "f"(f));
    return u;
}

// Sniff flags from the first 64 words (in shared). Deterministic.
__device__ __forceinline__ void sniff_flags(const unsigned* sv, int* flags) {
    bool allint = true, allfloat = true;
    for (int i = 0; i < 64; i++) {
        unsigned u = sv[i];
        if (u > 1u) allint = false;
        if (!(u == 0u || u == 0x3F800000u)) allfloat = false;
    }
    flags[0] = allint; flags[1] = allfloat;
}

// One merged prep kernel.
// Blocks [0,256): weight fragment packing (skip inactive experts).
// Blocks [256, 256+nab): A fragment packing per (mblock32, a) tile.
// Block 256+nab: mask compaction + s-permutation + ticket reset (parallel decode).
__global__ void prep_pack(const float* __restrict__ W1, const float* __restrict__ b1,
                          const float* __restrict__ W2, const float* __restrict__ b2,
                          const float* __restrict__ W3, const float* __restrict__ b3,
                          const float* __restrict__ act,
                          const unsigned* __restrict__ rel, int nab) {
    __shared__ float sbuf[8192];
    const int bx = blockIdx.x;
    const int tid = threadIdx.x;

    if (bx < 256) {
        // ---- local activity check (early-exit saves ~half the traffic) ----
        __shared__ unsigned sv[64];
        __shared__ int flags[2];
        __shared__ int s_active;
        if (tid < 64) sv[tid] = rel[tid];
        __syncthreads();
        if (tid == 0) {
            sniff_flags(sv, flags);
            int e = bx;
            if (flags[0])      s_active = (((const int*)rel)[e] != 0);
            else if (flags[1]) s_active = (((const float*)rel)[e] != 0.0f);
            else               s_active = (((const unsigned char*)rel)[e] != 0);
        }
        __syncthreads();
        if (!s_active) return;

        const int e = bx;
        float* dst = g_wpack + (size_t)e * PK_STRIDE;
        // ---- W1: K=128 x N=64, NP=4 ----
        {
            const float4* s = (const float4*)(W1 + (size_t)e * (DA_ * H_));
            for (int i = tid; i < 2048; i += 256) ((float4*)sbuf)[i] = s[i];
            __syncthreads();
            for (int cell = tid; cell < 2048; cell += 256) {
                int lane = cell & 31, g = cell >> 5;
                int kc = g >> 2, np = g & 3;
                int kb = kc * 8 + (lane & 3), nb = np * 16 + (lane >> 2);
                uint4 u;
                u.x = f2tf(sbuf[(kb + 0) * 64 + nb]);
                u.y = f2tf(sbuf[(kb + 4) * 64 + nb]);
                u.z = f2tf(sbuf[(kb + 0) * 64 + nb + 8]);
                u.w = f2tf(sbuf[(kb + 4) * 64 + nb + 8]);
                ((uint4*)(dst + PK_W1))[cell] = u;
            }
            __syncthreads();
        }
        // ---- W2: K=64 x N=64, NP=4 ----
        {
            const float4* s = (const float4*)(W2 + (size_t)e * (H_ * H_));
            for (int i = tid; i < 1024; i += 256) ((float4*)sbuf)[i] = s[i];
            __syncthreads();
            for (int cell = tid; cell < 1024; cell += 256) {
                int lane = cell & 31, g = cell >> 5;
                int kc = g >> 2, np = g & 3;
                int kb = kc * 8 + (lane & 3), nb = np * 16 + (lane >> 2);
                uint4 u;
                u.x = f2tf(sbuf[(kb + 0) * 64 + nb]);
                u.y = f2tf(sbuf[(kb + 4) * 64 + nb]);
                u.z = f2tf(sbuf[(kb + 0) * 64 + nb + 8]);
                u.w = f2tf(sbuf[(kb + 4) * 64 + nb + 8]);
                ((uint4*)(dst + PK_W2))[cell] = u;
            }
            __syncthreads();
        }
        // ---- W3: K=64 x N=128, NP=8 ----
        {
            const float4* s = (const float4*)(W3 + (size_t)e * (H_ * DS_));
            for (int i = tid; i < 2048; i += 256) ((float4*)sbuf)[i] = s[i];
            __syncthreads();
            for (int cell = tid; cell < 2048; cell += 256) {
                int lane = cell & 31, g = cell >> 5;
                int kc = g >> 3, np = g & 7;
                int kb = kc * 8 + (lane & 3), nb = np * 16 + (lane >> 2);
                uint4 u;
                u.x = f2tf(sbuf[(kb + 0) * 128 + nb]);
                u.y = f2tf(sbuf[(kb + 4) * 128 + nb]);
                u.z = f2tf(sbuf[(kb + 0) * 128 + nb + 8]);
                u.w = f2tf(sbuf[(kb + 4) * 128 + nb + 8]);
                ((uint4*)(dst + PK_W3))[cell] = u;
            }
        }
        if (tid < 64)        dst[PK_B1 + tid]        = b1[e * H_  + tid];
        else if (tid < 128)  dst[PK_B2 + tid - 64]   = b2[e * H_  + tid - 64];
        else if (tid < 256)  dst[PK_B3 + tid - 128]  = b3[e * DS_ + tid - 128];
    } else if (bx < 256 + nab) {
        const int t = bx - 256;
        const int mb = t >> 4, a = t & 15;
        const float* srcb = act + ((size_t)(mb * 32) * A_ + a) * DA_;
        for (int i = tid; i < 1024; i += 256) {
            int row = i >> 5, c4 = i & 31;
            *(float4*)(sbuf + row * 128 + c4 * 4) =
                *(const float4*)(srcb + (size_t)row * A_ * DA_ + c4 * 4);
        }
        __syncthreads();
        unsigned* dst = g_apack + ((size_t)mb * A_ + a) * 4096;
        for (int cell = tid; cell < 1024; cell += 256) {
            int lane = cell & 31, mt = (cell >> 5) & 1, kc = cell >> 6;
            int rl = mt * 16 + (lane >> 2), k = kc * 8 + (lane & 3);
            uint4 u;
            u.x = f2tf(sbuf[rl * 128 + k]);
            u.y = f2tf(sbuf[(rl + 8) * 128 + k]);
            u.z = f2tf(sbuf[rl * 128 + k + 4]);
            u.w = f2tf(sbuf[(rl + 8) * 128 + k + 4]);
            ((uint4*)dst)[cell] = u;
        }
    } else {
        // ---- mask compaction + sperm + ticket reset (PARALLEL decode) ----
        __shared__ unsigned sv[64];
        __shared__ int sm_[S_ * A_];
        __shared__ int flags[2];
        if (tid < 64) sv[tid] = rel[tid];
        __syncthreads();
        if (tid == 0) sniff_flags(sv, flags);
        __syncthreads();

        if (flags[0]) {
            sm_[tid] = (((const int*)rel)[tid] != 0);          // parallel
        } else if (flags[1]) {
            sm_[tid] = (((const float*)rel)[tid] != 0.0f);     // parallel
        } else {
            if (tid < 64) {
                unsigned u = sv[tid];
                sm_[tid * 4 + 0] = ((u      ) & 0xFF) != 0;
                sm_[tid * 4 + 1] = ((u >>  8) & 0xFF) != 0;
                sm_[tid * 4 + 2] = ((u >> 16) & 0xFF) != 0;
                sm_[tid * 4 + 3] = ((u >> 24) & 0xFF) != 0;
            }
        }
        __syncthreads();

        if (tid == 0) {
            g_ticket = 0;
            int cnt[S_];
            for (int s = 0; s < S_; s++) {
                int c = 0;
                for (int a = 0; a < A_; a++)
                    if (sm_[s * A_ + a]) g_list[s][c++] = a;
                g_cnt[s] = c;
                cnt[s] = c;
            }
            int perm[S_];
            for (int i = 0; i < S_; i++) perm[i] = i;
            for (int i = 0; i < S_ - 1; i++) {
                int best = i;
                for (int j = i + 1; j < S_; j++)
                    if (cnt[perm[j]] > cnt[perm[best]]) best = j;
                int tt = perm[i]; perm[i] = perm[best]; perm[best] = tt;
            }
            for (int i = 0; i < S_; i++) g_sperm[i] = perm[i];
        }
    }
}

__device__ __forceinline__ void cpa16(uint32_t dst, const void* src) {
    asm volatile("cp.async.cg.shared.global [%0], [%1], 16;" :: "r"(dst), "l"(src));
}
#define CP_COMMIT() asm volatile("cp.async.commit_group;" ::: "memory")
#define CP_WAIT2()  asm volatile("cp.async.wait_group 2;" ::: "memory")

__device__ __forceinline__ void mma_tf32(float& d0, float& d1, float& d2, float& d3,
                                         unsigned a0, unsigned a1, unsigned a2, unsigned a3,
                                         unsigned b0, unsigned b1) {
    asm volatile(
        "mma.sync.aligned.m16n8k8.row.col.f32.tf32.tf32.f32 "
        "{%0,%1,%2,%3}, {%4,%5,%6,%7}, {%8,%9}, {%0,%1,%2,%3};"
        : "+f"(d0), "+f"(d1), "+f"(d2), "+f"(d3)
        : "r"(a0), "r"(a1), "r"(a2), "r"(a3), "r"(b0), "r"(b1));
}

// --- staging: pure linear copies from packed image (128 threads) ---
__device__ __forceinline__ void stage1(uint32_t sb, int tid, const float* src) {
    #pragma unroll
    for (int it = 0; it < 16; it++) {
        int i = tid + it * NTHREADS;
        cpa16(sb + SM_W1 + i * 16, src + PK_W1 + i * 4);
    }
    if (tid < 16) cpa16(sb + SM_B1 + tid * 16, src + PK_B1 + tid * 4);
}
__device__ __forceinline__ void stage2(uint32_t sb, int tid, const float* src) {
    #pragma unroll
    for (int it = 0; it < 8; it++) {
        int i = tid + it * NTHREADS;
        cpa16(sb + SM_W2 + i * 16, src + PK_W2 + i * 4);
    }
    if (tid < 16) cpa16(sb + SM_B2 + tid * 16, src + PK_B2 + tid * 4);
}
__device__ __forceinline__ void stage3(uint32_t sb, int tid, const float* src) {
    #pragma unroll
    for (int it = 0; it < 16; it++) {
        int i = tid + it * NTHREADS;
        cpa16(sb + SM_W3 + i * 16, src + PK_W3 + i * 4);
    }
    if (tid < 32) cpa16(sb + SM_B3 + tid * 16, src + PK_B3 + tid * 4);
}

__global__ __launch_bounds__(NTHREADS, 2)
void expert_kernel(const float* __restrict__ state, float* __restrict__ out,
                   int nitems)
{
    extern __shared__ char smem[];
    const uint32_t sb = (uint32_t)__cvta_generic_to_shared(smem);
    const unsigned* W1u = (const unsigned*)(smem + SM_W1);
    const unsigned* W2u = (const unsigned*)(smem + SM_W2);
    const unsigned* W3u = (const unsigned*)(smem + SM_W3);
    float*    hs  = (float*)(smem + SM_H);
    const unsigned* hu = (const unsigned*)(smem + SM_H);
    const float* b1s = (const float*)(smem + SM_B1);
    const float* b2s = (const float*)(smem + SM_B2);
    const float* b3s = (const float*)(smem + SM_B3);
    int* tks = (int*)(smem + SM_TK);

    const int tid  = threadIdx.x;
    const int lane = tid & 31;
    const int warp = tid >> 5;
    const int wm   = warp & 1;      // 2 warp-rows (m32)
    const int wn   = warp >> 1;     // 2 warp-cols
    const int r    = lane >> 2;
    const int q    = lane & 3;
    const int mrow0 = wm * 32 + r;

    for (;;) {
        // ---- dynamic work ticket ----
        if (tid == 0) tks[0] = atomicAdd(&g_ticket, 1);
        __syncthreads();
        const int item = tks[0];
        if (item >= nitems) break;
        const int s  = g_sperm[item >> 5];
        const int b0 = (item & 31) * TB;
        const int bxq = item & 31;
        __syncthreads();   // tks consumed; prior item fully done with smem

        float acc[2][8][4];
        #pragma unroll
        for (int mt = 0; mt < 2; mt++)
            #pragma unroll
            for (int nt = 0; nt < 8; nt++)
                #pragma unroll
                for (int c = 0; c < 4; c++) acc[mt][nt][c] = 0.0f;

        const int cnt = g_cnt[s];

        if (cnt > 0) {
            const float* src = g_wpack + (size_t)(s * A_ + g_list[s][0]) * PK_STRIDE;
            stage1(sb, tid, src); CP_COMMIT();
            stage2(sb, tid, src); CP_COMMIT();
            stage3(sb, tid, src); CP_COMMIT();
        }

        for (int j = 0; j < cnt; j++) {
            const int a = g_list[s][j];
            const float* srcn = (j + 1 < cnt)
                ? g_wpack + (size_t)(s * A_ + g_list[s][j + 1]) * PK_STRIDE : nullptr;

            CP_WAIT2();          // W1(j), b1(j) landed
            __syncthreads();     // publish W1; everyone done with h/W3 from prev iter

            // ---- GEMM1: h1 = relu(A @ W1 + b1), M64 N64 K128 ----
            {
                float d[2][4][4];
                #pragma unroll
                for (int mt = 0; mt < 2; mt++)
                    #pragma unroll
                    for (int nt = 0; nt < 4; nt++)
                        { d[mt][nt][0]=0; d[mt][nt][1]=0; d[mt][nt][2]=0; d[mt][nt][3]=0; }

                const unsigned* atile =
                    g_apack + ((size_t)(bxq * 2 + wm) * A_ + a) * 4096;

                #pragma unroll 4
                for (int kc = 0; kc < 16; kc++) {
                    uint4 A0 = *(const uint4*)(atile + ((kc * 2 + 0) * 32 + lane) * 4);
                    uint4 A1 = *(const uint4*)(atile + ((kc * 2 + 1) * 32 + lane) * 4);
                    uint4 p0 = *(const uint4*)(W1u + ((kc * 4 + wn * 2 + 0) * 32 + lane) * 4);
                    uint4 p1 = *(const uint4*)(W1u + ((kc * 4 + wn * 2 + 1) * 32 + lane) * 4);
                    unsigned bf[4][2];
                    bf[0][0] = p0.x; bf[0][1] = p0.y; bf[1][0] = p0.z; bf[1][1] = p0.w;
                    bf[2][0] = p1.x; bf[2][1] = p1.y; bf[3][0] = p1.z; bf[3][1] = p1.w;
                    #pragma unroll
                    for (int nt = 0; nt < 4; nt++) {
                        mma_tf32(d[0][nt][0], d[0][nt][1], d[0][nt][2], d[0][nt][3],
                                 A0.x, A0.y, A0.z, A0.w, bf[nt][0], bf[nt][1]);
                        mma_tf32(d[1][nt][0], d[1][nt][1], d[1][nt][2], d[1][nt][3],
                                 A1.x, A1.y, A1.z, A1.w, bf[nt][0], bf[nt][1]);
                    }
                }
                #pragma unroll
                for (int mt = 0; mt < 2; mt++)
                    #pragma unroll
                    for (int nt = 0; nt < 4; nt++) {
                        int col = wn * 32 + nt * 8 + 2 * q;
                        float bb0 = b1s[col], bb1 = b1s[col + 1];
                        int row = mrow0 + mt * 16;
                        uint2 v0 = { f2tf(fmaxf(d[mt][nt][0] + bb0, 0.0f)),
                                     f2tf(fmaxf(d[mt][nt][1] + bb1, 0.0f)) };
                        uint2 v1 = { f2tf(fmaxf(d[mt][nt][2] + bb0, 0.0f)),
                                     f2tf(fmaxf(d[mt][nt][3] + bb1, 0.0f)) };
                        *(uint2*)(hs + row * H_LD + col)       = v0;
                        *(uint2*)(hs + (row + 8) * H_LD + col) = v1;
                    }
            }
            __syncthreads();     // ALL warps done reading W1(j)/b1(j) before overwrite
            if (srcn) { stage1(sb, tid, srcn); }
            CP_COMMIT();
            CP_WAIT2();          // W2(j), b2(j) landed
            __syncthreads();     // publish W2; h1 visible to all warps

            // ---- GEMM2: h2 = relu(h1 @ W2 + b2), M64 N64 K64 (in-place h) ----
            {
                unsigned a2r[8][2][4];
                #pragma unroll
                for (int kc = 0; kc < 8; kc++) {
                    const int k0 = kc * 8;
                    #pragma unroll
                    for (int mt = 0; mt < 2; mt++) {
                        const unsigned* hb = hu + (mrow0 + mt * 16) * H_LD + k0 + q;
                        a2r[kc][mt][0] = hb[0];
                        a2r[kc][mt][1] = hb[8 * H_LD];
                        a2r[kc][mt][2] = hb[4];
                        a2r[kc][mt][3] = hb[8 * H_LD + 4];
                    }
                }
                __syncthreads();   // all reads of h1 done; safe to overwrite

                float d[2][4][4];
                #pragma unroll
                for (int mt = 0; mt < 2; mt++)
                    #pragma unroll
                    for (int nt = 0; nt < 4; nt++)
                        { d[mt][nt][0]=0; d[mt][nt][1]=0; d[mt][nt][2]=0; d[mt][nt][3]=0; }
                #pragma unroll
                for (int kc = 0; kc < 8; kc++) {
                    unsigned bf[4][2];
                    uint4 p0 = *(const uint4*)(W2u + ((kc * 4 + wn * 2 + 0) * 32 + lane) * 4);
                    uint4 p1 = *(const uint4*)(W2u + ((kc * 4 + wn * 2 + 1) * 32 + lane) * 4);
                    bf[0][0] = p0.x; bf[0][1] = p0.y; bf[1][0] = p0.z; bf[1][1] = p0.w;
                    bf[2][0] = p1.x; bf[2][1] = p1.y; bf[3][0] = p1.z; bf[3][1] = p1.w;
                    #pragma unroll
                    for (int mt = 0; mt < 2; mt++)
                        #pragma unroll
                        for (int nt = 0; nt < 4; nt++)
                            mma_tf32(d[mt][nt][0], d[mt][nt][1], d[mt][nt][2], d[mt][nt][3],
                                     a2r[kc][mt][0], a2r[kc][mt][1], a2r[kc][mt][2], a2r[kc][mt][3],
                                     bf[nt][0], bf[nt][1]);
                }
                #pragma unroll
                for (int mt = 0; mt < 2; mt++)
                    #pragma unroll
                    for (int nt = 0; nt < 4; nt++) {
                        int col = wn * 32 + nt * 8 + 2 * q;
                        float bb0 = b2s[col], bb1 = b2s[col + 1];
                        int row = mrow0 + mt * 16;
                        uint2 v0 = { f2tf(fmaxf(d[mt][nt][0] + bb0, 0.0f)),
                                     f2tf(fmaxf(d[mt][nt][1] + bb1, 0.0f)) };
                        uint2 v1 = { f2tf(fmaxf(d[mt][nt][2] + bb0, 0.0f)),
                                     f2tf(fmaxf(d[mt][nt][3] + bb1, 0.0f)) };
                        *(uint2*)(hs + row * H_LD + col)       = v0;
                        *(uint2*)(hs + (row + 8) * H_LD + col) = v1;
                    }
            }
            __syncthreads();     // ALL warps done reading W2(j)/b2(j) before overwrite
            if (srcn) { stage2(sb, tid, srcn); }
            CP_COMMIT();
            CP_WAIT2();          // W3(j), b3(j) landed
            __syncthreads();     // publish W3; h2 visible to all warps

            // ---- GEMM3: acc += relu(h2 @ W3 + b3), M64 N128 K64 ----
            {
                float d[2][8][4];
                #pragma unroll
                for (int mt = 0; mt < 2; mt++)
                    #pragma unroll
                    for (int nt = 0; nt < 8; nt++)
                        { d[mt][nt][0]=0; d[mt][nt][1]=0; d[mt][nt][2]=0; d[mt][nt][3]=0; }
                #pragma unroll 2
                for (int kc = 0; kc < 8; kc++) {
                    const int k0 = kc * 8;
                    unsigned af[2][4], bf[8][2];
                    #pragma unroll
                    for (int mt = 0; mt < 2; mt++) {
                        const unsigned* hb = hu + (mrow0 + mt * 16) * H_LD + k0 + q;
                        af[mt][0] = hb[0];
                        af[mt][1] = hb[8 * H_LD];
                        af[mt][2] = hb[4];
                        af[mt][3] = hb[8 * H_LD + 4];
                    }
                    #pragma unroll
                    for (int pp = 0; pp < 4; pp++) {
                        uint4 p = *(const uint4*)(W3u + ((kc * 8 + wn * 4 + pp) * 32 + lane) * 4);
                        bf[2 * pp][0]     = p.x; bf[2 * pp][1]     = p.y;
                        bf[2 * pp + 1][0] = p.z; bf[2 * pp + 1][1] = p.w;
                    }
                    #pragma unroll
                    for (int mt = 0; mt < 2; mt++)
                        #pragma unroll
                        for (int nt = 0; nt < 8; nt++)
                            mma_tf32(d[mt][nt][0], d[mt][nt][1], d[mt][nt][2], d[mt][nt][3],
                                     af[mt][0], af[mt][1], af[mt][2], af[mt][3],
                                     bf[nt][0], bf[nt][1]);
                }
                #pragma unroll
                for (int mt = 0; mt < 2; mt++)
                    #pragma unroll
                    for (int nt = 0; nt < 8; nt++) {
                        int col = wn * 64 + nt * 8 + 2 * q;
                        float bb0 = b3s[col], bb1 = b3s[col + 1];
                        acc[mt][nt][0] += fmaxf(d[mt][nt][0] + bb0, 0.0f);
                        acc[mt][nt][1] += fmaxf(d[mt][nt][1] + bb1, 0.0f);
                        acc[mt][nt][2] += fmaxf(d[mt][nt][2] + bb0, 0.0f);
                        acc[mt][nt][3] += fmaxf(d[mt][nt][3] + bb1, 0.0f);
                    }
            }
            __syncthreads();     // ALL warps done reading W3(j)/b3(j)/h2 before overwrite
            if (srcn) { stage3(sb, tid, srcn); }
            CP_COMMIT();
        }

        // ---- epilogue: out = state + diff ----
        #pragma unroll
        for (int mt = 0; mt < 2; mt++)
            #pragma unroll
            for (int nt = 0; nt < 8; nt++) {
                int row = b0 + mrow0 + mt * 16;
                int col = wn * 64 + nt * 8 + 2 * q;
                size_t base = ((size_t)row * S_ + s) * DS_ + col;
                float2 s0 = *(const float2*)(state + base);
                float2 s1 = *(const float2*)(state + base + 8 * (size_t)S_ * DS_);
                float2 o0 = { s0.x + acc[mt][nt][0], s0.y + acc[mt][nt][1] };
                float2 o1 = { s1.x + acc[mt][nt][2], s1.y + acc[mt][nt][3] };
                *(float2*)(out + base)                        = o0;
                *(float2*)(out + base + 8 * (size_t)S_ * DS_) = o1;
            }
        __syncthreads();   // all warps done with W3/h before next item's staging
    }
}

extern "C" void kernel_launch(void* const* d_in, const int* in_sizes, int n_in,
                              void* d_out, int out_size)
{
    const float* state = (const float*)d_in[0];
    const float* act   = (const float*)d_in[1];
    const void*  rel   = d_in[2];
    const float* W1 = (const float*)d_in[3];
    const float* b1 = (const float*)d_in[4];
    const float* W2 = (const float*)d_in[5];
    const float* b2 = (const float*)d_in[6];
    const float* W3 = (const float*)d_in[7];
    const float* b3 = (const float*)d_in[8];
    float* out = (float*)d_out;

    const int B = in_sizes[0] / (S_ * DS_);
    const int nab = (B / 32) * A_;
    const int nitems = (B / TB) * S_;

    cudaFuncSetAttribute(expert_kernel,
                         cudaFuncAttributeMaxDynamicSharedMemorySize, SMEM_BYTES);

    prep_pack<<<256 + nab + 1, 256>>>(W1, b1, W2, b2, W3, b3, act,
                                      (const unsigned*)rel, nab);

    expert_kernel<<<NCTA_PERSIST, NTHREADS, SMEM_BYTES>>>(state, out, nitems);
}